// round 1
// baseline (speedup 1.0000x reference)
#include <cuda_runtime.h>
#include <math.h>

// Problem constants (fixed by the dataset)
#define N_   8192
#define C_   19
#define M_   10
#define CM_  190     // C_*M_
#define K_   64
#define NT   16      // n-rows per block in the fast kernel
#define TPB  192     // threads per block in the fast kernel (>= CM_)

// ---------------- device scratch (static globals: no allocation) -----------
__device__ int   d_flag;            // 1 => proto_var is uniform (fast path valid)
__device__ float d_v0;              // the uniform proto_var value
__device__ float d_r   [N_ * K_];   // 1 / (x_var + v0)
__device__ float d_a2  [N_ * K_];   // -2 * x * r
__device__ float d_base[N_];        // sum_k ( x^2 * r + log(x_var + v0) )

// ---------------- kernel 1: uniformity check -------------------------------
__global__ void check_uniform_kernel(const float* __restrict__ pv, int n) {
    float v0 = pv[0];
    int ok = 1;
    for (int i = threadIdx.x; i < n; i += blockDim.x) {
        ok &= (pv[i] == v0);
    }
    int all_ok = __syncthreads_and(ok);
    if (threadIdx.x == 0) {
        d_flag = all_ok ? 1 : 0;
        d_v0   = v0;
    }
}

// ---------------- kernel 2: per-(n,k) precompute ----------------------------
// 256 threads = 4 rows of n, 64 k-lanes each. Cheap regardless of flag.
__global__ void precompute_kernel(const float* __restrict__ x,
                                  const float* __restrict__ xv) {
    const int sub = threadIdx.x >> 6;       // 0..3 : which n in this block
    const int k   = threadIdx.x & 63;
    const int n   = blockIdx.x * 4 + sub;
    const float v0 = d_v0;

    const int g = n * K_ + k;
    const float xx = x[g];
    const float s  = xv[g] + v0;
    const float r  = 1.0f / s;
    d_r [g] = r;
    d_a2[g] = -2.0f * xx * r;

    float t = xx * xx * r + logf(s);

    // reduce 64 lanes (2 warps) per n
    #pragma unroll
    for (int off = 16; off; off >>= 1)
        t += __shfl_down_sync(0xffffffffu, t, off);

    __shared__ float red[8];                 // 2 warps per n * 4 n
    if ((k & 31) == 0) red[(sub << 1) | (k >> 5)] = t;
    __syncthreads();
    if (k == 0) d_base[n] = red[sub << 1] + red[(sub << 1) | 1];
}

// ---------------- kernel 3: fast path (uniform proto_var) ------------------
// thread = one cm (c*M+m) slot; block handles NT consecutive n rows.
// K split into 2 passes of 32 so prototype row halves live in registers.
__global__ void __launch_bounds__(TPB, 3)
fast_kernel(const float* __restrict__ proto, float* __restrict__ out) {
    if (!d_flag) return;

    __shared__ __align__(16) float rs[NT * 32];
    __shared__ __align__(16) float as[NT * 32];

    const int t  = threadIdx.x;
    const int cm = (t < CM_) ? t : 0;
    const int n0 = blockIdx.x * NT;

    float acc[NT];
    #pragma unroll
    for (int j = 0; j < NT; ++j) acc[j] = 0.0f;

    #pragma unroll
    for (int pass = 0; pass < 2; ++pass) {
        // prototype row half into registers (plus squared copy)
        float pk[32], p2k[32];
        const float4* prow =
            reinterpret_cast<const float4*>(proto + cm * K_ + pass * 32);
        #pragma unroll
        for (int q = 0; q < 8; ++q) {
            float4 v = __ldg(prow + q);
            pk [4*q+0] = v.x;  pk [4*q+1] = v.y;  pk [4*q+2] = v.z;  pk [4*q+3] = v.w;
            p2k[4*q+0] = v.x*v.x; p2k[4*q+1] = v.y*v.y;
            p2k[4*q+2] = v.z*v.z; p2k[4*q+3] = v.w*v.w;
        }

        __syncthreads();   // protect rs/as reuse across passes
        // stage r / a2 tile for this pass: NT rows x 32 k
        for (int idx = t; idx < NT * 32; idx += TPB) {
            const int j = idx >> 5;
            const int k = idx & 31;
            const int g = (n0 + j) * K_ + pass * 32 + k;
            rs[idx] = d_r [g];
            as[idx] = d_a2[g];
        }
        __syncthreads();

        for (int j = 0; j < NT; ++j) {
            float a = acc[j];
            const float4* r4 = reinterpret_cast<const float4*>(rs + j * 32);
            const float4* a4 = reinterpret_cast<const float4*>(as + j * 32);
            #pragma unroll
            for (int q = 0; q < 8; ++q) {
                float4 rv = r4[q];
                float4 av = a4[q];
                a = fmaf(p2k[4*q+0], rv.x, a);  a = fmaf(pk[4*q+0], av.x, a);
                a = fmaf(p2k[4*q+1], rv.y, a);  a = fmaf(pk[4*q+1], av.y, a);
                a = fmaf(p2k[4*q+2], rv.z, a);  a = fmaf(pk[4*q+2], av.z, a);
                a = fmaf(p2k[4*q+3], rv.w, a);  a = fmaf(pk[4*q+3], av.w, a);
            }
            acc[j] = a;
        }
    }

    if (t < CM_) {
        #pragma unroll
        for (int j = 0; j < NT; ++j) {
            const int n = n0 + j;
            out[n * CM_ + cm] = -0.0078125f * (acc[j] + d_base[n]); // -0.5/64
        }
    }
}

// ---------------- kernel 4: general fallback (non-uniform proto_var) -------
__global__ void fallback_kernel(const float* __restrict__ x,
                                const float* __restrict__ xv,
                                const float* __restrict__ p,
                                const float* __restrict__ pv,
                                float* __restrict__ out) {
    if (d_flag) return;   // uniform case handled by fast path
    const int total = N_ * CM_;
    for (int idx = blockIdx.x * blockDim.x + threadIdx.x; idx < total;
         idx += gridDim.x * blockDim.x) {
        const int n  = idx / CM_;
        const int cm = idx % CM_;
        float acc = 0.0f;
        for (int k = 0; k < K_; ++k) {
            const float s = xv[n * K_ + k] + pv[cm * K_ + k];
            const float d = p[cm * K_ + k] - x[n * K_ + k];
            acc += d * d / s + logf(s);
        }
        out[idx] = -0.5f * acc * (1.0f / (float)K_);
    }
}

// ---------------- launch ----------------------------------------------------
extern "C" void kernel_launch(void* const* d_in, const int* in_sizes, int n_in,
                              void* d_out, int out_size) {
    const float* x  = (const float*)d_in[0];   // [8192,64]
    const float* xv = (const float*)d_in[1];   // [8192,64]
    const float* p  = (const float*)d_in[2];   // [19,10,64]
    const float* pv = (const float*)d_in[3];   // [19,10,64]
    float* out = (float*)d_out;                // [8192,19,10]

    check_uniform_kernel<<<1, 256>>>(pv, C_ * M_ * K_);
    precompute_kernel<<<N_ / 4, 256>>>(x, xv);
    fast_kernel<<<N_ / NT, TPB>>>(p, out);
    fallback_kernel<<<296, 256>>>(x, xv, p, pv, out);
}

// round 2
// speedup vs baseline: 1.9200x; 1.9200x over previous
#include <cuda_runtime.h>
#include <math.h>

// Problem constants (fixed by the dataset)
#define N_   8192
#define C_   19
#define M_   10
#define CM_  190          // C_*M_
#define K_   64
#define NT   16           // n-rows per block
#define TPB  192          // threads per block (>= CM_)
#define PVN  (C_*M_*K_)   // 12160

__device__ int d_flag;    // 1 => proto_var uniform (fast path valid)

// ---- packed f32x2 helpers (Blackwell FFMA2) --------------------------------
__device__ __forceinline__ unsigned long long
fma2(unsigned long long a, unsigned long long b, unsigned long long c) {
    unsigned long long d;
    asm("fma.rn.f32x2 %0, %1, %2, %3;" : "=l"(d) : "l"(a), "l"(b), "l"(c));
    return d;
}
__device__ __forceinline__ unsigned long long
mul2(unsigned long long a, unsigned long long b) {
    unsigned long long d;
    asm("mul.rn.f32x2 %0, %1, %2;" : "=l"(d) : "l"(a), "l"(b));
    return d;
}
__device__ __forceinline__ unsigned long long d2u(double v) {
    return __double_as_longlong(v);
}

// ---- kernel 1: uniformity check (single block, recomputed every call) ------
__global__ void check_kernel(const float* __restrict__ pv) {
    const float v0 = pv[0];
    int ok = 1;
    #pragma unroll 4
    for (int i = threadIdx.x; i < PVN; i += 1024)
        ok &= (pv[i] == v0);
    const int all = __syncthreads_and(ok);
    if (threadIdx.x == 0) d_flag = all;
}

// ---- kernel 2: fused precompute + mainloop (+ general fallback branch) -----
__global__ void __launch_bounds__(TPB, 2)
main_kernel(const float* __restrict__ x,  const float* __restrict__ xv,
            const float* __restrict__ p,  const float* __restrict__ pv,
            float* __restrict__ out) {
    __shared__ __align__(16) float rs[NT * K_];   // 1/(xv+v0)        4 KB
    __shared__ __align__(16) float as[NT * K_];   // -2*x/(xv+v0)     4 KB
    __shared__ float base_s[NT];                  // sum_k x^2 r + log s

    const int t  = threadIdx.x;
    const int n0 = blockIdx.x * NT;

    if (d_flag) {
        // ================= FAST PATH (uniform proto_var) =================
        const float v0 = __ldg(pv);

        if (t < NT) base_s[t] = 0.0f;
        __syncthreads();

        // --- block-local precompute: 16 rows x 64 k = 1024 elements ---
        // 192 threads -> 6 iterations; every warp covers one 32-aligned
        // half-row, so a full-warp shuffle reduce is segment-exact.
        #pragma unroll
        for (int it = 0; it < 6; ++it) {
            const int idx = t + it * TPB;
            const bool active = (idx < NT * K_);
            float tval = 0.0f;
            int row = 0;
            if (active) {
                row = idx >> 6;
                const int g = (n0 + row) * K_ + (idx & 63);
                const float xx = x[g];
                const float s  = xv[g] + v0;
                const float r  = 1.0f / s;
                rs[idx] = r;
                as[idx] = -2.0f * xx * r;
                tval = xx * xx * r + logf(s);
            }
            #pragma unroll
            for (int off = 16; off; off >>= 1)
                tval += __shfl_down_sync(0xffffffffu, tval, off);
            if (active && (t & 31) == 0) atomicAdd(&base_s[row], tval);
        }
        __syncthreads();

        // --- mainloop: packed-pair dot products --------------------------
        const int cm = (t < CM_) ? t : 0;

        unsigned long long acc[NT];
        #pragma unroll
        for (int j = 0; j < NT; ++j) acc[j] = 0ull;

        #pragma unroll
        for (int pass = 0; pass < 2; ++pass) {
            // prototype half-row (32 floats = 16 packed pairs) + squares
            unsigned long long pk[16], p2[16];
            const double2* prow =
                reinterpret_cast<const double2*>(p + cm * K_ + pass * 32);
            #pragma unroll
            for (int q = 0; q < 8; ++q) {
                const double2 v = __ldg(prow + q);
                pk[2*q]   = d2u(v.x);
                pk[2*q+1] = d2u(v.y);
            }
            #pragma unroll
            for (int i = 0; i < 16; ++i) p2[i] = mul2(pk[i], pk[i]);

            #pragma unroll
            for (int j = 0; j < NT; ++j) {
                unsigned long long a = acc[j];
                const double2* r2 =
                    reinterpret_cast<const double2*>(rs + j * K_ + pass * 32);
                const double2* a2 =
                    reinterpret_cast<const double2*>(as + j * K_ + pass * 32);
                #pragma unroll
                for (int q = 0; q < 8; ++q) {
                    const double2 rv = r2[q];
                    const double2 av = a2[q];
                    a = fma2(p2[2*q],   d2u(rv.x), a);
                    a = fma2(p2[2*q+1], d2u(rv.y), a);
                    a = fma2(pk[2*q],   d2u(av.x), a);
                    a = fma2(pk[2*q+1], d2u(av.y), a);
                }
                acc[j] = a;
            }
        }

        if (t < CM_) {
            #pragma unroll
            for (int j = 0; j < NT; ++j) {
                const double ad = __longlong_as_double(acc[j]);
                const float2 f2 = *reinterpret_cast<const float2*>(&ad);
                out[(n0 + j) * CM_ + cm] =
                    -0.0078125f * (f2.x + f2.y + base_s[j]);  // -0.5/64
            }
        }
    } else {
        // ================= GENERAL FALLBACK (non-uniform pv) ============
        for (int idx = t; idx < NT * CM_; idx += TPB) {
            const int j  = idx / CM_;
            const int cm = idx % CM_;
            const int n  = n0 + j;
            float acc = 0.0f;
            for (int k = 0; k < K_; ++k) {
                const float s = xv[n * K_ + k] + pv[cm * K_ + k];
                const float d = p[cm * K_ + k] - x[n * K_ + k];
                acc += d * d / s + logf(s);
            }
            out[n * CM_ + cm] = -0.5f * acc * (1.0f / (float)K_);
        }
    }
}

// ---- launch -----------------------------------------------------------------
extern "C" void kernel_launch(void* const* d_in, const int* in_sizes, int n_in,
                              void* d_out, int out_size) {
    const float* x  = (const float*)d_in[0];   // [8192,64]
    const float* xv = (const float*)d_in[1];   // [8192,64]
    const float* p  = (const float*)d_in[2];   // [19,10,64]
    const float* pv = (const float*)d_in[3];   // [19,10,64]
    float* out = (float*)d_out;                // [8192,19,10]

    check_kernel<<<1, 1024>>>(pv);
    main_kernel<<<N_ / NT, TPB>>>(x, xv, p, pv, out);
}